// round 4
// baseline (speedup 1.0000x reference)
#include <cuda_runtime.h>
#include <cstddef>

#define BB 64
#define SS 2048
#define II 64
#define HH 128

// Scratch: wx projected + biases folded, as float2 {wx+bg, wx+bu}. Padded by 4
// timesteps so the scan's prefetch ring can read unconditionally past the end.
__device__ __align__(16) float2 g_wx2[BB * SS * HH + 4 * HH];

// ---------------- packed f32x2 helpers ----------------
__device__ __forceinline__ unsigned long long ffma2(unsigned long long a,
                                                    unsigned long long b,
                                                    unsigned long long c) {
    unsigned long long d;
    asm("fma.rn.f32x2 %0, %1, %2, %3;" : "=l"(d) : "l"(a), "l"(b), "l"(c));
    return d;
}
__device__ __forceinline__ unsigned long long fadd2(unsigned long long a,
                                                    unsigned long long b) {
    unsigned long long d;
    asm("add.rn.f32x2 %0, %1, %2;" : "=l"(d) : "l"(a), "l"(b));
    return d;
}
__device__ __forceinline__ void unpack2(unsigned long long s, float& lo, float& hi) {
    asm("mov.b64 {%0, %1}, %2;" : "=f"(lo), "=f"(hi) : "l"(s));
}
__device__ __forceinline__ unsigned long long pack2(float lo, float hi) {
    unsigned long long r;
    asm("mov.b64 %0, {%1, %2};" : "=l"(r) : "f"(lo), "f"(hi));
    return r;
}

__device__ __forceinline__ float rcp_ap(float x) {
    float y;
    asm("rcp.approx.f32 %0, %1;" : "=f"(y) : "f"(x));
    return y;
}
__device__ __forceinline__ float tanh_ap(float x) {
    float y;
    asm("tanh.approx.f32 %0, %1;" : "=f"(y) : "f"(x));
    return y;
}
__device__ __forceinline__ float sigmf(float x) {
    return rcp_ap(1.0f + __expf(-x));
}

// ---------------- GEMM: Y[M,128] = X[M,K] @ W[K,128] -> g_wx2 (+bg/+bu) ------
// 128 threads. Thread t: column pair p = t>>1 -> cols (2p, 2p+1); half = t&1
// owns k-range [half*K/2, ...). W column-pairs in registers (f32x2). X rows
// staged duplicated ({v,v}) in SMEM -> LDS.128 + 2x FFMA2. shfl.bfly(1) reduce
// leaves thread t with column t; epilogue folds biases and writes float2.
template <int K>
__global__ void __launch_bounds__(128, 2)
gemm_wx_kernel(const float* __restrict__ X, const float* __restrict__ W,
               const float* __restrict__ bg, const float* __restrict__ bu,
               int rows_per_cta) {
    constexpr int KH = K / 2;
    constexpr int CHUNK = 32;
    __shared__ __align__(16) float2 xs[CHUNK][K + 4];

    const int tid = threadIdx.x;
    const int p = tid >> 1;
    const int half = tid & 1;

    unsigned long long wreg[KH];
#pragma unroll
    for (int k = 0; k < KH; k++) {
        wreg[k] = *reinterpret_cast<const unsigned long long*>(
            W + (size_t)(half * KH + k) * HH + 2 * p);
    }
    const float bgj = bg[tid];
    const float buj = bu[tid];

    const int row0 = blockIdx.x * rows_per_cta;

    for (int rc = 0; rc < rows_per_cta; rc += CHUNK) {
        __syncthreads();
        for (int idx = tid; idx < CHUNK * K; idx += 128) {
            int r = idx / K;
            int k = idx % K;
            float v = X[(size_t)(row0 + rc + r) * K + k];
            int slot = (k < KH) ? k : (k + 2);
            xs[r][slot] = make_float2(v, v);
        }
        __syncthreads();

#pragma unroll 2
        for (int r = 0; r < CHUNK; r++) {
            const ulonglong2* xp =
                reinterpret_cast<const ulonglong2*>(&xs[r][half * (KH + 2)]);
            unsigned long long a0 = 0, a1 = 0, a2 = 0, a3 = 0;
#pragma unroll
            for (int i = 0; i < KH / 2; i++) {
                ulonglong2 v = xp[i];
                if (i & 1) {
                    a2 = ffma2(v.x, wreg[2 * i], a2);
                    a3 = ffma2(v.y, wreg[2 * i + 1], a3);
                } else {
                    a0 = ffma2(v.x, wreg[2 * i], a0);
                    a1 = ffma2(v.y, wreg[2 * i + 1], a1);
                }
            }
            unsigned long long s = fadd2(fadd2(a0, a2), fadd2(a1, a3));
            float lo, hi;
            unpack2(s, lo, hi);
            float olo = __shfl_xor_sync(0xffffffffu, lo, 1);
            float ohi = __shfl_xor_sync(0xffffffffu, hi, 1);
            float y = half ? (hi + ohi) : (lo + olo);
            g_wx2[(size_t)(row0 + rc + r) * HH + tid] =
                make_float2(y + bgj, y + buj);
        }
    }
}

// ---------------- Recurrent scan: one batch row per CTA, 128 threads --------
// Thread j owns column j end-to-end: u column packed by k-pairs in 64 f32x2
// registers, h[128] plain in SMEM ping-pong (all loads broadcast), no shuffles.
// One __syncthreads per step. wx (with biases folded) via 4-deep LDG ring.
__global__ void __launch_bounds__(128, 1)
scan_kernel(const float* __restrict__ u, const float* __restrict__ zeta,
            const float* __restrict__ nu, const float* __restrict__ lambd,
            const float* __restrict__ gamma, float* __restrict__ out,
            float* __restrict__ hT) {
    const int b = blockIdx.x;
    const int j = threadIdx.x;

    __shared__ __align__(16) float hbuf[2][HH];

    unsigned long long ureg[64];
#pragma unroll
    for (int m = 0; m < 64; m++) {
        ureg[m] = pack2(u[(size_t)(2 * m) * HH + j],
                        u[(size_t)(2 * m + 1) * HH + j]);
    }

    const float sz = sigmf(zeta[0]);
    const float sn = sigmf(nu[0]);
    const float szn = sz + sn;
    const float gc = fminf(fmaxf(gamma[0], 0.0f), 1.0f);
    const float omgl = (1.0f - gc) * lambd[0];

    hbuf[0][j] = 0.0f;
    float h_old = 0.0f;

    const float2* wxb = g_wx2 + (size_t)b * SS * HH + j;
    float* outb = out + (size_t)b * SS * HH + j;

    float2 ring[4];
#pragma unroll
    for (int i = 0; i < 4; i++) ring[i] = __ldg(wxb + (size_t)i * HH);

    __syncthreads();

    int buf = 0;
#pragma unroll 2
    for (int s = 0; s < SS; s++) {
        float2 wxv = ring[s & 3];
        ring[s & 3] = __ldg(wxb + (size_t)(s + 4) * HH);  // padded; no branch

        const ulonglong2* hp = reinterpret_cast<const ulonglong2*>(hbuf[buf]);
        unsigned long long a0 = 0, a1 = 0, a2 = 0, a3 = 0;
#pragma unroll
        for (int i = 0; i < 32; i++) {
            ulonglong2 v = hp[i];
            if (i & 1) {
                a2 = ffma2(v.x, ureg[2 * i], a2);
                a3 = ffma2(v.y, ureg[2 * i + 1], a3);
            } else {
                a0 = ffma2(v.x, ureg[2 * i], a0);
                a1 = ffma2(v.y, ureg[2 * i + 1], a1);
            }
        }
        unsigned long long ssum = fadd2(fadd2(a0, a2), fadd2(a1, a3));
        float lo, hi;
        unpack2(ssum, lo, hi);
        float mv = lo + hi;

        float preg = mv + wxv.x;            // wx + bg
        float preu = mv + wxv.y;            // wx + bu
        float hh = tanh_ap(preu);           // MUFU, overlaps z chain
        float z = sigmf(preg);              // ex2 + rcp
        // z*h + (sz*(1-z)+sn)*hh  ==  z*(h - sz*hh) + (sz+sn)*hh
        float hnew = fmaf(z, fmaf(-sz, hh, h_old), szn * hh);
        float hc = fmaf(gc, hnew, omgl);
        h_old = hc;

        hbuf[buf ^ 1][j] = hc;
        __syncthreads();
        outb[(size_t)s * HH] = hc;          // off critical path
        buf ^= 1;
    }

    hT[b * HH + j] = h_old;
}

// ---------------- launch ----------------
extern "C" void kernel_launch(void* const* d_in, const int* in_sizes, int n_in,
                              void* d_out, int out_size) {
    const float* x      = (const float*)d_in[0];
    const float* w0     = (const float*)d_in[1];
    const float* u0     = (const float*)d_in[2];
    const float* bg0    = (const float*)d_in[3];
    const float* bu0    = (const float*)d_in[4];
    const float* zeta0  = (const float*)d_in[5];
    const float* nu0    = (const float*)d_in[6];
    const float* lambd0 = (const float*)d_in[7];
    const float* gamma0 = (const float*)d_in[8];
    const float* w1     = (const float*)d_in[9];
    const float* u1     = (const float*)d_in[10];
    const float* bg1    = (const float*)d_in[11];
    const float* bu1    = (const float*)d_in[12];
    const float* zeta1  = (const float*)d_in[13];
    const float* nu1    = (const float*)d_in[14];
    const float* lambd1 = (const float*)d_in[15];
    const float* gamma1 = (const float*)d_in[16];

    float* out = (float*)d_out;                  // out1 region [B*S*H]
    float* h0T = out + (size_t)BB * SS * HH;     // h_n[0]
    float* h1T = h0T + (size_t)BB * HH;          // h_n[1]

    const int M = BB * SS;       // 131072 rows
    const int GRID = 1024;
    const int RPC = M / GRID;    // 128 rows per CTA

    // Layer 0
    gemm_wx_kernel<II><<<GRID, 128>>>(x, w0, bg0, bu0, RPC);
    scan_kernel<<<BB, 128>>>(u0, zeta0, nu0, lambd0, gamma0, out, h0T);

    // Layer 1
    gemm_wx_kernel<HH><<<GRID, 128>>>(out, w1, bg1, bu1, RPC);
    scan_kernel<<<BB, 128>>>(u1, zeta1, nu1, lambd1, gamma1, out, h1T);
}

// round 5
// speedup vs baseline: 1.0130x; 1.0130x over previous
#include <cuda_runtime.h>
#include <cstddef>

#define BB 64
#define SS 2048
#define II 64
#define HH 128

// wx1 = out0 @ w1, produced on-the-fly by the layer-0 fused kernel,
// consumed by the layer-1 scan. out0 itself never goes to DRAM.
__device__ float g_wx[BB * SS * HH];

// ---------------- packed f32x2 helpers ----------------
__device__ __forceinline__ unsigned long long ffma2(unsigned long long a,
                                                    unsigned long long b,
                                                    unsigned long long c) {
    unsigned long long d;
    asm("fma.rn.f32x2 %0, %1, %2, %3;" : "=l"(d) : "l"(a), "l"(b), "l"(c));
    return d;
}
__device__ __forceinline__ unsigned long long fadd2(unsigned long long a,
                                                    unsigned long long b) {
    unsigned long long d;
    asm("add.rn.f32x2 %0, %1, %2;" : "=l"(d) : "l"(a), "l"(b));
    return d;
}
__device__ __forceinline__ void unpack2(unsigned long long s, float& lo, float& hi) {
    asm("mov.b64 {%0, %1}, %2;" : "=f"(lo), "=f"(hi) : "l"(s));
}
__device__ __forceinline__ unsigned long long pack2(float lo, float hi) {
    unsigned long long r;
    asm("mov.b64 %0, {%1, %2};" : "=l"(r) : "f"(lo), "f"(hi));
    return r;
}

__device__ __forceinline__ float sigmf(float x) {
    return __fdividef(1.0f, 1.0f + __expf(-x));
}
__device__ __forceinline__ float tanhf_fast(float x) {
    x = fminf(fmaxf(x, -15.0f), 15.0f);
    float e = __expf(-2.0f * x);
    return __fdividef(1.0f - e, 1.0f + e);
}

#define CTA_BAR() asm volatile("bar.sync 0, 256;" ::: "memory")

// ============ Kernel A: layer-0 scan fused with both projections ============
// 256 threads, one batch row per CTA.
//   warps 0-3 (tid<128): R1 scan verbatim; wx0 comes from SMEM ring (wxr).
//   warps 4-7 (pt=tid-128): projection workers.
//     - stage x rows (ring of 8) via float4 LDG (pt<16)
//     - wx0[s+2] = x[b,s+2,:] @ w0  -> wxr ring (SMEM)
//     - wx1[s-1] = out0[b,s-1,:] @ w1 -> g_wx (DRAM), out0 read from hplain
// One bar.sync 0,256 per iteration; both role branches execute identical
// barrier counts (2 prologue + 2048 loop).
__global__ void __launch_bounds__(256, 1)
layer0_fused(const float* __restrict__ x, const float* __restrict__ w0,
             const float* __restrict__ u, const float* __restrict__ bg,
             const float* __restrict__ bu, const float* __restrict__ zeta,
             const float* __restrict__ nu, const float* __restrict__ lambd,
             const float* __restrict__ gamma, const float* __restrict__ w1,
             float* __restrict__ hT) {
    const int b = blockIdx.x;
    const int tid = threadIdx.x;

    __shared__ __align__(16) float2 hdup[2][2][66];   // scan's duplicated-h ping-pong
    __shared__ __align__(16) float hplain[2][HH];     // plain h for projections
    __shared__ __align__(16) float xr[8][II];         // x-row ring
    __shared__ __align__(16) float wxr[4][HH];        // wx0 ring

    if (tid < 128) {
        // ---------------- scan role (R1 verbatim) ----------------
        const int p = tid >> 1;
        const int half = tid & 1;
        const int kbase = half * 64;

        unsigned long long ureg[64];
#pragma unroll
        for (int kk = 0; kk < 64; kk++) {
            ureg[kk] = *reinterpret_cast<const unsigned long long*>(
                u + (size_t)(kbase + kk) * HH + 2 * p);
        }

        const float bgj = bg[tid];
        const float buj = bu[tid];
        const float sz = sigmf(zeta[0]);
        const float sn = sigmf(nu[0]);
        const float gc = fminf(fmaxf(gamma[0], 0.0f), 1.0f);
        const float omgl = (1.0f - gc) * lambd[0];

        hdup[0][tid >> 6][tid & 63] = make_float2(0.0f, 0.0f);
        hplain[0][tid] = 0.0f;
        float h_old = 0.0f;

        CTA_BAR();  // B1
        CTA_BAR();  // B2

        int buf = 0;
#pragma unroll 4
        for (int s = 0; s < SS; s++) {
            float wxv = wxr[s & 3][tid];

            const ulonglong2* hp =
                reinterpret_cast<const ulonglong2*>(&hdup[buf][half][0]);
            unsigned long long a0 = 0, a1 = 0, a2 = 0, a3 = 0;
#pragma unroll
            for (int i = 0; i < 32; i++) {
                ulonglong2 v = hp[i];
                if (i & 1) {
                    a2 = ffma2(v.x, ureg[2 * i], a2);
                    a3 = ffma2(v.y, ureg[2 * i + 1], a3);
                } else {
                    a0 = ffma2(v.x, ureg[2 * i], a0);
                    a1 = ffma2(v.y, ureg[2 * i + 1], a1);
                }
            }
            unsigned long long ssum = fadd2(fadd2(a0, a2), fadd2(a1, a3));
            float lo, hi;
            unpack2(ssum, lo, hi);
            float olo = __shfl_xor_sync(0xffffffffu, lo, 1);
            float ohi = __shfl_xor_sync(0xffffffffu, hi, 1);
            float pre = (half ? (hi + ohi) : (lo + olo)) + wxv;

            float z = sigmf(pre + bgj);
            float hh = tanhf_fast(pre + buj);
            float hnew = z * h_old + (sz * (1.0f - z) + sn) * hh;
            float hc = gc * hnew + omgl;
            h_old = hc;

            hdup[buf ^ 1][tid >> 6][tid & 63] = make_float2(hc, hc);
            hplain[buf ^ 1][tid] = hc;
            CTA_BAR();
            buf ^= 1;
        }

        hT[b * HH + tid] = h_old;
    } else {
        // ---------------- projection role ----------------
        const int pt = tid - 128;  // 0..127 -> output column

        unsigned long long w0reg[32];
#pragma unroll
        for (int m = 0; m < 32; m++) {
            w0reg[m] = pack2(w0[(size_t)(2 * m) * HH + pt],
                             w0[(size_t)(2 * m + 1) * HH + pt]);
        }
        unsigned long long w1reg[64];
#pragma unroll
        for (int m = 0; m < 64; m++) {
            w1reg[m] = pack2(w1[(size_t)(2 * m) * HH + pt],
                             w1[(size_t)(2 * m + 1) * HH + pt]);
        }

        const float* xb = x + (size_t)b * SS * II;
        float4 pend[2];
        if (pt < 16) {
            // stage rows 0..5 directly; rows 6,7 pending in regs
#pragma unroll
            for (int r = 0; r < 6; r++) {
                *reinterpret_cast<float4*>(&xr[r][pt * 4]) =
                    *reinterpret_cast<const float4*>(xb + (size_t)r * II + pt * 4);
            }
            pend[0] = *reinterpret_cast<const float4*>(xb + (size_t)6 * II + pt * 4);
            pend[1] = *reinterpret_cast<const float4*>(xb + (size_t)7 * II + pt * 4);
        }

        CTA_BAR();  // B1

        // prologue: wx0[0] and wx0[1]
#pragma unroll
        for (int t = 0; t < 2; t++) {
            const ulonglong2* xp = reinterpret_cast<const ulonglong2*>(xr[t]);
            unsigned long long a0 = 0, a1 = 0;
#pragma unroll
            for (int i = 0; i < 16; i++) {
                ulonglong2 v = xp[i];
                a0 = ffma2(v.x, w0reg[2 * i], a0);
                a1 = ffma2(v.y, w0reg[2 * i + 1], a1);
            }
            float lo, hi;
            unpack2(fadd2(a0, a1), lo, hi);
            wxr[t][pt] = lo + hi;
        }

        CTA_BAR();  // B2

        float* gwb = g_wx + (size_t)b * SS * HH + pt;

        for (int s = 0; s < SS; s++) {
            // x staging: commit pending row s+6, fetch row s+8
            if (pt < 16) {
                *reinterpret_cast<float4*>(&xr[(s + 6) & 7][pt * 4]) = pend[s & 1];
                if (s + 8 < SS) {
                    pend[s & 1] = *reinterpret_cast<const float4*>(
                        xb + (size_t)(s + 8) * II + pt * 4);
                }
            }

            // wx0 for row s+2 (consumed by scan at iter s+2)
            {
                const ulonglong2* xp =
                    reinterpret_cast<const ulonglong2*>(xr[(s + 2) & 7]);
                unsigned long long a0 = 0, a1 = 0;
#pragma unroll
                for (int i = 0; i < 16; i++) {
                    ulonglong2 v = xp[i];
                    a0 = ffma2(v.x, w0reg[2 * i], a0);
                    a1 = ffma2(v.y, w0reg[2 * i + 1], a1);
                }
                float lo, hi;
                unpack2(fadd2(a0, a1), lo, hi);
                wxr[(s + 2) & 3][pt] = lo + hi;
            }

            // wx1 for timestep s-1: out0[s-1] == hplain[s&1]
            if (s > 0) {
                const ulonglong2* hp =
                    reinterpret_cast<const ulonglong2*>(hplain[s & 1]);
                unsigned long long a0 = 0, a1 = 0, a2 = 0, a3 = 0;
#pragma unroll
                for (int i = 0; i < 32; i++) {
                    ulonglong2 v = hp[i];
                    if (i & 1) {
                        a2 = ffma2(v.x, w1reg[2 * i], a2);
                        a3 = ffma2(v.y, w1reg[2 * i + 1], a3);
                    } else {
                        a0 = ffma2(v.x, w1reg[2 * i], a0);
                        a1 = ffma2(v.y, w1reg[2 * i + 1], a1);
                    }
                }
                float lo, hi;
                unpack2(fadd2(fadd2(a0, a2), fadd2(a1, a3)), lo, hi);
                gwb[(size_t)(s - 1) * HH] = lo + hi;
            }

            CTA_BAR();
        }

        // epilogue: wx1[2047] from final state (hplain[0], written at iter 2047)
        {
            const ulonglong2* hp = reinterpret_cast<const ulonglong2*>(hplain[0]);
            unsigned long long a0 = 0, a1 = 0, a2 = 0, a3 = 0;
#pragma unroll
            for (int i = 0; i < 32; i++) {
                ulonglong2 v = hp[i];
                if (i & 1) {
                    a2 = ffma2(v.x, w1reg[2 * i], a2);
                    a3 = ffma2(v.y, w1reg[2 * i + 1], a3);
                } else {
                    a0 = ffma2(v.x, w1reg[2 * i], a0);
                    a1 = ffma2(v.y, w1reg[2 * i + 1], a1);
                }
            }
            float lo, hi;
            unpack2(fadd2(fadd2(a0, a2), fadd2(a1, a3)), lo, hi);
            gwb[(size_t)(SS - 1) * HH] = lo + hi;
        }
    }
}

// ============ Kernel B: layer-1 scan (R1 verbatim, reads g_wx) ============
__global__ void __launch_bounds__(128, 1)
scan_kernel(const float* __restrict__ u, const float* __restrict__ bg,
            const float* __restrict__ bu, const float* __restrict__ zeta,
            const float* __restrict__ nu, const float* __restrict__ lambd,
            const float* __restrict__ gamma, float* __restrict__ out,
            float* __restrict__ hT) {
    const int b = blockIdx.x;
    const int tid = threadIdx.x;
    const int p = tid >> 1;
    const int half = tid & 1;
    const int kbase = half * 64;

    __shared__ __align__(16) float2 hbuf[2][2][66];

    unsigned long long ureg[64];
#pragma unroll
    for (int kk = 0; kk < 64; kk++) {
        ureg[kk] = *reinterpret_cast<const unsigned long long*>(
            u + (size_t)(kbase + kk) * HH + 2 * p);
    }

    const float bgj = bg[tid];
    const float buj = bu[tid];
    const float sz = sigmf(zeta[0]);
    const float sn = sigmf(nu[0]);
    const float gc = fminf(fmaxf(gamma[0], 0.0f), 1.0f);
    const float omgl = (1.0f - gc) * lambd[0];

    hbuf[0][tid >> 6][tid & 63] = make_float2(0.0f, 0.0f);
    float h_old = 0.0f;

    const float* wxb = g_wx + (size_t)b * SS * HH + tid;
    float* outb = out + (size_t)b * SS * HH + tid;

    float ring[4];
#pragma unroll
    for (int i = 0; i < 4; i++) ring[i] = wxb[i * HH];

    __syncthreads();

    int buf = 0;
#pragma unroll 4
    for (int s = 0; s < SS; s++) {
        float wxv = ring[s & 3];
        if (s + 4 < SS) ring[s & 3] = __ldg(wxb + (size_t)(s + 4) * HH);

        const ulonglong2* hp =
            reinterpret_cast<const ulonglong2*>(&hbuf[buf][half][0]);
        unsigned long long a0 = 0, a1 = 0, a2 = 0, a3 = 0;
#pragma unroll
        for (int i = 0; i < 32; i++) {
            ulonglong2 v = hp[i];
            if (i & 1) {
                a2 = ffma2(v.x, ureg[2 * i], a2);
                a3 = ffma2(v.y, ureg[2 * i + 1], a3);
            } else {
                a0 = ffma2(v.x, ureg[2 * i], a0);
                a1 = ffma2(v.y, ureg[2 * i + 1], a1);
            }
        }
        unsigned long long ssum = fadd2(fadd2(a0, a2), fadd2(a1, a3));
        float lo, hi;
        unpack2(ssum, lo, hi);
        float olo = __shfl_xor_sync(0xffffffffu, lo, 1);
        float ohi = __shfl_xor_sync(0xffffffffu, hi, 1);
        float pre = (half ? (hi + ohi) : (lo + olo)) + wxv;

        float z = sigmf(pre + bgj);
        float hh = tanhf_fast(pre + buj);
        float hnew = z * h_old + (sz * (1.0f - z) + sn) * hh;
        float hc = gc * hnew + omgl;
        h_old = hc;

        outb[(size_t)s * HH] = hc;
        hbuf[buf ^ 1][tid >> 6][tid & 63] = make_float2(hc, hc);
        __syncthreads();
        buf ^= 1;
    }

    hT[b * HH + tid] = h_old;
}

// ---------------- launch ----------------
extern "C" void kernel_launch(void* const* d_in, const int* in_sizes, int n_in,
                              void* d_out, int out_size) {
    const float* x      = (const float*)d_in[0];
    const float* w0     = (const float*)d_in[1];
    const float* u0     = (const float*)d_in[2];
    const float* bg0    = (const float*)d_in[3];
    const float* bu0    = (const float*)d_in[4];
    const float* zeta0  = (const float*)d_in[5];
    const float* nu0    = (const float*)d_in[6];
    const float* lambd0 = (const float*)d_in[7];
    const float* gamma0 = (const float*)d_in[8];
    const float* w1     = (const float*)d_in[9];
    const float* u1     = (const float*)d_in[10];
    const float* bg1    = (const float*)d_in[11];
    const float* bu1    = (const float*)d_in[12];
    const float* zeta1  = (const float*)d_in[13];
    const float* nu1    = (const float*)d_in[14];
    const float* lambd1 = (const float*)d_in[15];
    const float* gamma1 = (const float*)d_in[16];

    float* out = (float*)d_out;                  // out1 region [B*S*H]
    float* h0T = out + (size_t)BB * SS * HH;     // h_n[0]
    float* h1T = h0T + (size_t)BB * HH;          // h_n[1]

    // Layer 0 fused: scan0 + wx0 on-the-fly + wx1 -> g_wx, h0T
    layer0_fused<<<BB, 256>>>(x, w0, u0, bg0, bu0, zeta0, nu0, lambd0, gamma0,
                              w1, h0T);
    // Layer 1: scan over g_wx -> out, h1T
    scan_kernel<<<BB, 128>>>(u1, bg1, bu1, zeta1, nu1, lambd1, gamma1, out, h1T);
}

// round 6
// speedup vs baseline: 1.6145x; 1.5938x over previous
#include <cuda_runtime.h>
#include <cstddef>

#define BB 64
#define SS 2048
#define II 64
#define HH 128

// 64 MB scratch for the precomputed input projection wx = X @ W (both layers)
__device__ float g_wx[BB * SS * HH];

// ---------------- packed f32x2 helpers ----------------
__device__ __forceinline__ unsigned long long ffma2(unsigned long long a,
                                                    unsigned long long b,
                                                    unsigned long long c) {
    unsigned long long d;
    asm("fma.rn.f32x2 %0, %1, %2, %3;" : "=l"(d) : "l"(a), "l"(b), "l"(c));
    return d;
}
__device__ __forceinline__ unsigned long long fadd2(unsigned long long a,
                                                    unsigned long long b) {
    unsigned long long d;
    asm("add.rn.f32x2 %0, %1, %2;" : "=l"(d) : "l"(a), "l"(b));
    return d;
}
__device__ __forceinline__ void unpack2(unsigned long long s, float& lo, float& hi) {
    asm("mov.b64 {%0, %1}, %2;" : "=f"(lo), "=f"(hi) : "l"(s));
}
// duplicate a scalar into both lanes of an f32x2 (ALU pipe, 1 instr)
__device__ __forceinline__ unsigned long long dup2(float v) {
    unsigned long long r;
    asm("mov.b64 %0, {%1, %1};" : "=l"(r) : "f"(v));
    return r;
}

__device__ __forceinline__ float sigmf(float x) {
    return __fdividef(1.0f, 1.0f + __expf(-x));
}
__device__ __forceinline__ float tanh_ap(float x) {
    float y;
    asm("tanh.approx.f32 %0, %1;" : "=f"(y) : "f"(x));
    return y;
}

// ---------------- GEMM: Y[M,128] = X[M,K] @ W[K,128] -> g_wx ----------------
// 128 threads. Thread t: column pair p = t>>1 -> cols (2p, 2p+1); half = t&1
// owns k-range [half*K/2, ...). W column-pairs in registers (f32x2). X rows
// staged PLAIN in SMEM (coalesced float4 copy); inner loop: LDS.128 (4 x vals)
// + 4x in-register dup (ALU) + 4x FFMA2 -> FMA-pipe bound, LDS pressure 1:4.
// shfl.bfly(1) reduce leaves thread t with column t.
template <int K>
__global__ void __launch_bounds__(128, 2)
gemm_wx_kernel(const float* __restrict__ X, const float* __restrict__ W,
               int rows_per_cta) {
    constexpr int KH = K / 2;
    constexpr int CHUNK = 32;
    __shared__ __align__(16) float xs[CHUNK][K];

    const int tid = threadIdx.x;
    const int p = tid >> 1;
    const int half = tid & 1;

    unsigned long long wreg[KH];
#pragma unroll
    for (int k = 0; k < KH; k++) {
        wreg[k] = *reinterpret_cast<const unsigned long long*>(
            W + (size_t)(half * KH + k) * HH + 2 * p);
    }

    const int row0 = blockIdx.x * rows_per_cta;

    for (int rc = 0; rc < rows_per_cta; rc += CHUNK) {
        __syncthreads();  // previous chunk fully consumed
        const float4* src =
            reinterpret_cast<const float4*>(X + (size_t)(row0 + rc) * K);
        float4* dst = reinterpret_cast<float4*>(&xs[0][0]);
        for (int i = tid; i < CHUNK * K / 4; i += 128) dst[i] = src[i];
        __syncthreads();

#pragma unroll 2
        for (int r = 0; r < CHUNK; r++) {
            const float4* xp = reinterpret_cast<const float4*>(&xs[r][half * KH]);
            unsigned long long a0 = 0, a1 = 0, a2 = 0, a3 = 0;
#pragma unroll
            for (int i = 0; i < KH / 4; i++) {
                float4 v = xp[i];
                a0 = ffma2(dup2(v.x), wreg[4 * i + 0], a0);
                a1 = ffma2(dup2(v.y), wreg[4 * i + 1], a1);
                a2 = ffma2(dup2(v.z), wreg[4 * i + 2], a2);
                a3 = ffma2(dup2(v.w), wreg[4 * i + 3], a3);
            }
            unsigned long long s = fadd2(fadd2(a0, a2), fadd2(a1, a3));
            float lo, hi;
            unpack2(s, lo, hi);
            float olo = __shfl_xor_sync(0xffffffffu, lo, 1);
            float ohi = __shfl_xor_sync(0xffffffffu, hi, 1);
            float y = half ? (hi + ohi) : (lo + olo);
            g_wx[(size_t)(row0 + rc + r) * HH + tid] = y;
        }
    }
}

// ---------------- Recurrent scan (one CTA per batch row) ----------------
// R1-verbatim structure; ONLY the activation math changed:
//   z  = 0.5 + 0.5*tanh(0.5*(pre+bg))   (1 MUFU vs exp+rcp)
//   hh = tanh.approx(pre+bu)            (1 MUFU vs 2 MUFU + div)
__global__ void __launch_bounds__(128, 1)
scan_kernel(const float* __restrict__ u, const float* __restrict__ bg,
            const float* __restrict__ bu, const float* __restrict__ zeta,
            const float* __restrict__ nu, const float* __restrict__ lambd,
            const float* __restrict__ gamma, float* __restrict__ out,
            float* __restrict__ hT) {
    const int b = blockIdx.x;
    const int tid = threadIdx.x;
    const int p = tid >> 1;
    const int half = tid & 1;
    const int kbase = half * 64;

    __shared__ __align__(16) float2 hbuf[2][2][66];  // [pingpong][k-half][slot]

    unsigned long long ureg[64];
#pragma unroll
    for (int kk = 0; kk < 64; kk++) {
        ureg[kk] = *reinterpret_cast<const unsigned long long*>(
            u + (size_t)(kbase + kk) * HH + 2 * p);
    }

    const float bgj_h = 0.5f * bg[tid];
    const float buj = bu[tid];
    const float sz = sigmf(zeta[0]);
    const float sn = sigmf(nu[0]);
    const float gc = fminf(fmaxf(gamma[0], 0.0f), 1.0f);
    const float omgl = (1.0f - gc) * lambd[0];

    hbuf[0][tid >> 6][tid & 63] = make_float2(0.0f, 0.0f);
    float h_old = 0.0f;

    const float* wxb = g_wx + (size_t)b * SS * HH + tid;
    float* outb = out + (size_t)b * SS * HH + tid;

    float ring[4];
#pragma unroll
    for (int i = 0; i < 4; i++) ring[i] = wxb[i * HH];

    __syncthreads();

    int buf = 0;
#pragma unroll 4
    for (int s = 0; s < SS; s++) {
        float wxv = ring[s & 3];
        if (s + 4 < SS) ring[s & 3] = __ldg(wxb + (size_t)(s + 4) * HH);

        const ulonglong2* hp =
            reinterpret_cast<const ulonglong2*>(&hbuf[buf][half][0]);
        unsigned long long a0 = 0, a1 = 0, a2 = 0, a3 = 0;
#pragma unroll
        for (int i = 0; i < 32; i++) {
            ulonglong2 v = hp[i];
            if (i & 1) {
                a2 = ffma2(v.x, ureg[2 * i], a2);
                a3 = ffma2(v.y, ureg[2 * i + 1], a3);
            } else {
                a0 = ffma2(v.x, ureg[2 * i], a0);
                a1 = ffma2(v.y, ureg[2 * i + 1], a1);
            }
        }
        unsigned long long ssum = fadd2(fadd2(a0, a2), fadd2(a1, a3));
        float lo, hi;
        unpack2(ssum, lo, hi);
        float olo = __shfl_xor_sync(0xffffffffu, lo, 1);
        float ohi = __shfl_xor_sync(0xffffffffu, hi, 1);
        float pre = (half ? (hi + ohi) : (lo + olo)) + wxv;

        float z = fmaf(tanh_ap(fmaf(0.5f, pre, bgj_h)), 0.5f, 0.5f);
        float hh = tanh_ap(pre + buj);
        float hnew = z * h_old + (sz * (1.0f - z) + sn) * hh;
        float hc = gc * hnew + omgl;
        h_old = hc;

        outb[(size_t)s * HH] = hc;
        hbuf[buf ^ 1][tid >> 6][tid & 63] = make_float2(hc, hc);
        __syncthreads();
        buf ^= 1;
    }

    hT[b * HH + tid] = h_old;
}

// ---------------- launch ----------------
extern "C" void kernel_launch(void* const* d_in, const int* in_sizes, int n_in,
                              void* d_out, int out_size) {
    const float* x      = (const float*)d_in[0];
    const float* w0     = (const float*)d_in[1];
    const float* u0     = (const float*)d_in[2];
    const float* bg0    = (const float*)d_in[3];
    const float* bu0    = (const float*)d_in[4];
    const float* zeta0  = (const float*)d_in[5];
    const float* nu0    = (const float*)d_in[6];
    const float* lambd0 = (const float*)d_in[7];
    const float* gamma0 = (const float*)d_in[8];
    const float* w1     = (const float*)d_in[9];
    const float* u1     = (const float*)d_in[10];
    const float* bg1    = (const float*)d_in[11];
    const float* bu1    = (const float*)d_in[12];
    const float* zeta1  = (const float*)d_in[13];
    const float* nu1    = (const float*)d_in[14];
    const float* lambd1 = (const float*)d_in[15];
    const float* gamma1 = (const float*)d_in[16];

    float* out = (float*)d_out;                  // out1 region [B*S*H]
    float* h0T = out + (size_t)BB * SS * HH;     // h_n[0]
    float* h1T = h0T + (size_t)BB * HH;          // h_n[1]

    const int M = BB * SS;       // 131072 rows
    const int GRID = 1024;
    const int RPC = M / GRID;    // 128 rows per CTA

    // Layer 0: wx0 = x @ w0 -> g_wx ; scan0 -> out (as out0 scratch) + h0T
    gemm_wx_kernel<II><<<GRID, 128>>>(x, w0, RPC);
    scan_kernel<<<BB, 128>>>(u0, bg0, bu0, zeta0, nu0, lambd0, gamma0, out, h0T);

    // Layer 1: wx1 = out0 @ w1 -> g_wx ; scan1 -> out (final) + h1T
    gemm_wx_kernel<HH><<<GRID, 128>>>(out, w1, RPC);
    scan_kernel<<<BB, 128>>>(u1, bg1, bu1, zeta1, nu1, lambd1, gamma1, out, h1T);
}

// round 9
// speedup vs baseline: 1.9769x; 1.2245x over previous
#include <cuda_runtime.h>
#include <cstddef>

#define BB 64
#define SS 2048
#define II 64
#define HH 128
#define DELTA 192
#define CHUNK64 64
#define NITER (SS + DELTA)

__device__ float g_wxA[BB * SS * HH];   // wx0 = x @ w0
__device__ float g_wxB[BB * SS * HH];   // wx1 = out0 @ w1
__device__ float g_out0[BB * SS * HH];  // layer-0 hidden states
__device__ int g_wprog[BB];             // wx0 rows published (worker -> scan0)
__device__ int g_sprog[BB];             // out0 rows published (scan0 -> worker)
__device__ int g_gprog[BB];             // wx1 rows published (worker -> scan1)

__device__ __forceinline__ unsigned long long ffma2(unsigned long long a,
                                                    unsigned long long b,
                                                    unsigned long long c) {
    unsigned long long d;
    asm("fma.rn.f32x2 %0, %1, %2, %3;" : "=l"(d) : "l"(a), "l"(b), "l"(c));
    return d;
}
__device__ __forceinline__ unsigned long long fadd2(unsigned long long a,
                                                    unsigned long long b) {
    unsigned long long d;
    asm("add.rn.f32x2 %0, %1, %2;" : "=l"(d) : "l"(a), "l"(b));
    return d;
}
__device__ __forceinline__ void unpack2(unsigned long long s, float& lo, float& hi) {
    asm("mov.b64 {%0, %1}, %2;" : "=f"(lo), "=f"(hi) : "l"(s));
}
__device__ __forceinline__ unsigned long long pack2(float lo, float hi) {
    unsigned long long r;
    asm("mov.b64 %0, {%1, %2};" : "=l"(r) : "f"(lo), "f"(hi));
    return r;
}
__device__ __forceinline__ float sigmf(float x) {
    return __fdividef(1.0f, 1.0f + __expf(-x));
}
__device__ __forceinline__ float tanh_ap(float x) {
    float y;
    asm("tanh.approx.f32 %0, %1;" : "=f"(y) : "f"(x));
    return y;
}

// Worker matvec: lanes = even/odd k partials (x plain, w packed by k-pairs).
// Collapsing lo+hi IS correct here.
template <int N2>
__device__ __forceinline__ float mv_row(const ulonglong2* xp,
                                        const unsigned long long* wreg) {
    unsigned long long a0 = 0, a1 = 0, a2 = 0, a3 = 0;
#pragma unroll
    for (int i = 0; i < N2; i++) {
        ulonglong2 v = xp[i];
        if (i & 1) {
            a2 = ffma2(v.x, wreg[2 * i], a2);
            a3 = ffma2(v.y, wreg[2 * i + 1], a3);
        } else {
            a0 = ffma2(v.x, wreg[2 * i], a0);
            a1 = ffma2(v.y, wreg[2 * i + 1], a1);
        }
    }
    float lo, hi;
    unpack2(fadd2(fadd2(a0, a2), fadd2(a1, a3)), lo, hi);
    return lo + hi;
}

__global__ void init_kernel() {
    int i = threadIdx.x;
    if (i < BB) {
        g_wprog[i] = 0;
        g_sprog[i] = 0;
        g_gprog[i] = 0;
    }
}

__global__ void __launch_bounds__(256, 1)
fused_kernel(const float* __restrict__ x, const float* __restrict__ w0,
             const float* __restrict__ w1,
             const float* __restrict__ u0, const float* __restrict__ bg0,
             const float* __restrict__ bu0, const float* __restrict__ zeta0,
             const float* __restrict__ nu0, const float* __restrict__ lambd0,
             const float* __restrict__ gamma0,
             const float* __restrict__ u1, const float* __restrict__ bg1,
             const float* __restrict__ bu1, const float* __restrict__ zeta1,
             const float* __restrict__ nu1, const float* __restrict__ lambd1,
             const float* __restrict__ gamma1,
             float* __restrict__ out, float* __restrict__ h0T,
             float* __restrict__ h1T) {
    const int tid = threadIdx.x;

    if (blockIdx.x < BB) {
        // ====== scanner CTA: layer0 (warps 0-3) + layer1 (warps 4-7) =========
        const int b = blockIdx.x;
        const int layer = tid >> 7;
        const int lt = tid & 127;
        const int p = lt >> 1;
        const int half = lt & 1;
        const int kbase = half * 64;

        __shared__ __align__(16) float2 hbuf[2][2][2][66];

        // ureg lanes = COLUMNS (2p, 2p+1); this thread's k-half only.
        const float* u = layer ? u1 : u0;
        unsigned long long ureg[64];
#pragma unroll
        for (int kk = 0; kk < 64; kk++) {
            ureg[kk] = *reinterpret_cast<const unsigned long long*>(
                u + (size_t)(kbase + kk) * HH + 2 * p);
        }

        const float bgj_h = 0.5f * (layer ? bg1 : bg0)[lt];
        const float buj = (layer ? bu1 : bu0)[lt];
        const float sz = sigmf((layer ? zeta1 : zeta0)[0]);
        const float sn = sigmf((layer ? nu1 : nu0)[0]);
        const float gc = fminf(fmaxf((layer ? gamma1 : gamma0)[0], 0.0f), 1.0f);
        const float omgl = (1.0f - gc) * (layer ? lambd1 : lambd0)[0];

        hbuf[layer][0][lt >> 6][lt & 63] = make_float2(0.0f, 0.0f);
        float h_old = 0.0f;

        const float* wxb = (layer ? g_wxB : g_wxA) + (size_t)b * SS * HH + lt;
        float* outb = (layer ? out : g_out0) + (size_t)b * SS * HH + lt;

        float ring[4] = {0.f, 0.f, 0.f, 0.f};
        int buf = 0;
        __syncthreads();

#pragma unroll 2
        for (int t = 0; t < NITER; t++) {
            if ((t & 63) == 0) {
                if (tid == 0) {
                    if (t < SS) {
                        int need = t + 72 < SS ? t + 72 : SS;
                        while (*(volatile int*)&g_wprog[b] < need) __nanosleep(64);
                    }
                    int s1w = t - DELTA;
                    if (s1w >= 0 && s1w < SS) {
                        int need = s1w + 72 < SS ? s1w + 72 : SS;
                        while (*(volatile int*)&g_gprog[b] < need) __nanosleep(64);
                    }
                    __threadfence();
                }
                __syncthreads();
            }

            const int s = t - (layer ? DELTA : 0);
            const bool act = (s >= 0) && (s < SS);
            if (act) {
                if (s == 0) {
#pragma unroll
                    for (int i = 0; i < 4; i++)
                        ring[i] = __ldg(wxb + (size_t)i * HH);
                }
                float wxv = ring[s & 3];
                if (s + 4 < SS) ring[s & 3] = __ldg(wxb + (size_t)(s + 4) * HH);

                // matvec: partial sums for columns (2p, 2p+1) over this k-half
                const ulonglong2* hp = reinterpret_cast<const ulonglong2*>(
                    &hbuf[layer][buf][half][0]);
                unsigned long long a0 = 0, a1 = 0, a2 = 0, a3 = 0;
#pragma unroll
                for (int i = 0; i < 32; i++) {
                    ulonglong2 v = hp[i];
                    if (i & 1) {
                        a2 = ffma2(v.x, ureg[2 * i], a2);
                        a3 = ffma2(v.y, ureg[2 * i + 1], a3);
                    } else {
                        a0 = ffma2(v.x, ureg[2 * i], a0);
                        a1 = ffma2(v.y, ureg[2 * i + 1], a1);
                    }
                }
                unsigned long long ssum = fadd2(fadd2(a0, a2), fadd2(a1, a3));
                float lo, hi;
                unpack2(ssum, lo, hi);
                // lanes are columns: combine k-halves via bfly, select own column
                float olo = __shfl_xor_sync(0xffffffffu, lo, 1);
                float ohi = __shfl_xor_sync(0xffffffffu, hi, 1);
                float pre = (half ? (hi + ohi) : (lo + olo)) + wxv;

                float z = fmaf(tanh_ap(fmaf(0.5f, pre, bgj_h)), 0.5f, 0.5f);
                float hh = tanh_ap(pre + buj);
                float hnew = z * h_old + (sz * (1.0f - z) + sn) * hh;
                float hc = gc * hnew + omgl;
                h_old = hc;

                outb[(size_t)s * HH] = hc;
                hbuf[layer][buf ^ 1][lt >> 6][lt & 63] = make_float2(hc, hc);
            }
            const bool pub = (t < SS) && ((t & 63) == 63);
            if (pub) __threadfence();   // all threads: order out0 stores
            __syncthreads();
            if (act) buf ^= 1;
            if (tid == 0 && pub) atomicExch(&g_sprog[b], t + 1);
        }

        if (layer == 0) h0T[b * HH + lt] = h_old;
        else h1T[b * HH + lt] = h_old;
    } else {
        // ====== worker CTA: streams wx0 (3 chunks ahead) and wx1 =============
        const int b = blockIdx.x - BB;
        const int j = tid & 127;
        const bool comp = tid < 128;

        __shared__ __align__(16) float xs[32][II];
        __shared__ __align__(16) float os[32][HH];

        // worker weights packed by k-pairs: lanes = even/odd k
        unsigned long long w0reg[32];
        unsigned long long w1reg[64];
        if (comp) {
#pragma unroll
            for (int m = 0; m < 32; m++)
                w0reg[m] = pack2(w0[(size_t)(2 * m) * HH + j],
                                 w0[(size_t)(2 * m + 1) * HH + j]);
#pragma unroll
            for (int m = 0; m < 64; m++)
                w1reg[m] = pack2(w1[(size_t)(2 * m) * HH + j],
                                 w1[(size_t)(2 * m + 1) * HH + j]);
        }

        auto produce_wx0 = [&](int c) {
            for (int sub = 0; sub < 2; sub++) {
                int r0 = c * CHUNK64 + sub * 32;
                const float4* src = reinterpret_cast<const float4*>(
                    x + ((size_t)b * SS + r0) * II);
                float4* dst = reinterpret_cast<float4*>(&xs[0][0]);
                for (int i = tid; i < 32 * II / 4; i += 256) dst[i] = src[i];
                __syncthreads();
                if (comp) {
                    for (int r = 0; r < 32; r++) {
                        float y = mv_row<16>(
                            reinterpret_cast<const ulonglong2*>(&xs[r][0]), w0reg);
                        g_wxA[((size_t)b * SS + r0 + r) * HH + j] = y;
                    }
                }
                __syncthreads();
            }
            __threadfence();            // all threads: order wx0 stores
            __syncthreads();
            if (tid == 0) atomicExch(&g_wprog[b], (c + 1) * CHUNK64);
        };

        auto produce_wx1 = [&](int c) {
            for (int sub = 0; sub < 2; sub++) {
                int r0 = c * CHUNK64 + sub * 32;
                const float4* src = reinterpret_cast<const float4*>(
                    g_out0 + ((size_t)b * SS + r0) * HH);
                float4* dst = reinterpret_cast<float4*>(&os[0][0]);
                for (int i = tid; i < 32 * HH / 4; i += 256) dst[i] = src[i];
                __syncthreads();
                if (comp) {
                    for (int r = 0; r < 32; r++) {
                        float y = mv_row<32>(
                            reinterpret_cast<const ulonglong2*>(&os[r][0]), w1reg);
                        g_wxB[((size_t)b * SS + r0 + r) * HH + j] = y;
                    }
                }
                __syncthreads();
            }
            __threadfence();            // all threads: order wx1 stores
            __syncthreads();
            if (tid == 0) atomicExch(&g_gprog[b], (c + 1) * CHUNK64);
        };

        produce_wx0(0);
        produce_wx0(1);
        produce_wx0(2);

        for (int c = 0; c < SS / CHUNK64; c++) {
            if (c + 3 < SS / CHUNK64) produce_wx0(c + 3);
            if (tid == 0) {
                int need = (c + 1) * CHUNK64;
                while (*(volatile int*)&g_sprog[b] < need) __nanosleep(128);
                __threadfence();
            }
            __syncthreads();
            produce_wx1(c);
        }
    }
}

extern "C" void kernel_launch(void* const* d_in, const int* in_sizes, int n_in,
                              void* d_out, int out_size) {
    const float* x      = (const float*)d_in[0];
    const float* w0     = (const float*)d_in[1];
    const float* u0     = (const float*)d_in[2];
    const float* bg0    = (const float*)d_in[3];
    const float* bu0    = (const float*)d_in[4];
    const float* zeta0  = (const float*)d_in[5];
    const float* nu0    = (const float*)d_in[6];
    const float* lambd0 = (const float*)d_in[7];
    const float* gamma0 = (const float*)d_in[8];
    const float* w1     = (const float*)d_in[9];
    const float* u1     = (const float*)d_in[10];
    const float* bg1    = (const float*)d_in[11];
    const float* bu1    = (const float*)d_in[12];
    const float* zeta1  = (const float*)d_in[13];
    const float* nu1    = (const float*)d_in[14];
    const float* lambd1 = (const float*)d_in[15];
    const float* gamma1 = (const float*)d_in[16];

    float* out = (float*)d_out;
    float* h0T = out + (size_t)BB * SS * HH;
    float* h1T = h0T + (size_t)BB * HH;

    init_kernel<<<1, 64>>>();
    fused_kernel<<<2 * BB, 256>>>(x, w0, w1,
                                  u0, bg0, bu0, zeta0, nu0, lambd0, gamma0,
                                  u1, bg1, bu1, zeta1, nu1, lambd1, gamma1,
                                  out, h0T, h1T);
}